// round 8
// baseline (speedup 1.0000x reference)
#include <cuda_runtime.h>

#define FEAT 161
#define HID  176
#define SEQB 456
#define NTHR 704
#define NCTA 128
#define NCLUS 64

// ---- float2-packed transposed weight offsets (float units) ----
// layout per region: float2 element (pair p, col c) at base + (p*Cp + c)*2
#define A1  0        // Wdh : 82 pairs, Cp=176
#define A2  28864    // Whr : 88 pairs, Cp=164
#define A3  57728    // Wfr : 82 pairs, Cp=164
#define A4  84624    // Wwc gx seg: 82 pairs, Cp=164
#define A4b 111520   // Wwc m  seg: 82 pairs, Cp=164
#define A5  138416   // LSTM1 cc seg: 82 pairs, Cp=704 (cols permuted)
#define A5m 253872   // LSTM1 m  seg: 82 pairs, Cp=704
#define A5h 369328   // LSTM1 h0 seg: 88 pairs, Cp=704
#define A6  493232   // LSTM2 h0 seg: 88 pairs, Cp=704
#define A6h 617136   // LSTM2 hd seg: 88 pairs, Cp=704
#define WT_TOTAL 741040

// ---- bias offsets ----
#define B_bdh 0
#define B_wdx 176
#define B_bdx 337
#define B_bhr 498
#define B_bfr 659
#define B_bwc 820
#define B_b1  981
#define B_b2  1685
#define B_Wo  2389
#define B_bo  2565
#define B_TOTAL 2566

#define SMEM_BYTES 103808

__device__ float g_WT[WT_TOTAL];
__device__ float g_B[B_TOTAL];
__device__ float g_inv_msum[SEQB];
__device__ float g_lossp[NCLUS];

// ============================= repack =====================================
__global__ void repack_kernel(
    const float* __restrict__ Wdh, const float* __restrict__ Whr,
    const float* __restrict__ Wfr, const float* __restrict__ Wwc,
    const float* __restrict__ Wih, const float* __restrict__ Whh,
    const float* __restrict__ Wih2, const float* __restrict__ Whh2,
    const float* __restrict__ bdh, const float* __restrict__ Wdx,
    const float* __restrict__ bdx, const float* __restrict__ bhr,
    const float* __restrict__ bfr, const float* __restrict__ bwc,
    const float* __restrict__ bih, const float* __restrict__ bhh,
    const float* __restrict__ bih2, const float* __restrict__ bhh2,
    const float* __restrict__ Wo, const float* __restrict__ bo)
{
    int stride = gridDim.x * blockDim.x;
    for (int idx = blockIdx.x * blockDim.x + threadIdx.x; idx < WT_TOTAL; idx += stride) {
        float v = 0.0f;
        int base, Cp, region;
        if      (idx < A2)  { base = A1;  Cp = 176; region = 0; }
        else if (idx < A3)  { base = A2;  Cp = 164; region = 1; }
        else if (idx < A4)  { base = A3;  Cp = 164; region = 2; }
        else if (idx < A4b) { base = A4;  Cp = 164; region = 3; }
        else if (idx < A5)  { base = A4b; Cp = 164; region = 4; }
        else if (idx < A5m) { base = A5;  Cp = 704; region = 5; }
        else if (idx < A5h) { base = A5m; Cp = 704; region = 6; }
        else if (idx < A6)  { base = A5h; Cp = 704; region = 7; }
        else if (idx < A6h) { base = A6;  Cp = 704; region = 8; }
        else                { base = A6h; Cp = 704; region = 9; }
        int j = idx - base, pc = j >> 1, half = j & 1;
        int p = pc / Cp, c = pc % Cp;
        int k = 2 * p + half;
        if (region >= 5) {
            // permuted LSTM column -> original gate row
            int rk = c / 352, rem = c % 352, q = rem / 88, jl = rem % 88;
            int r = q * 176 + rk * 88 + jl;
            switch (region) {
                case 5: if (k < 161) v = Wih[r * 322 + k]; break;
                case 6: if (k < 161) v = Wih[r * 322 + 161 + k]; break;
                case 7: v = Whh[r * 176 + k]; break;
                case 8: v = Wih2[r * 176 + k]; break;
                case 9: v = Whh2[r * 176 + k]; break;
            }
        } else {
            switch (region) {
                case 0: if (k < 161) v = Wdh[c * 161 + k]; break;
                case 1: if (c < 161) v = Whr[c * 176 + k]; break;
                case 2: if (c < 161 && k < 161 && k != c) v = Wfr[c * 161 + k]; break;
                case 3: if (c < 161 && k < 161) v = Wwc[c * 322 + k]; break;
                case 4: if (c < 161 && k < 161) v = Wwc[c * 322 + 161 + k]; break;
            }
        }
        g_WT[idx] = v;
    }
    for (int idx = blockIdx.x * blockDim.x + threadIdx.x; idx < B_TOTAL; idx += stride) {
        float v;
        if (idx < 176)        v = bdh[idx];
        else if (idx < 337)   { int f = idx - 176; v = Wdx[f * 161 + f]; }
        else if (idx < 498)   v = bdx[idx - 337];
        else if (idx < 659)   v = bhr[idx - 498];
        else if (idx < 820)   v = bfr[idx - 659];
        else if (idx < 981)   v = bwc[idx - 820];
        else if (idx < 1685)  {
            int j = idx - 981;
            int rk = j / 352, rem = j % 352, q = rem / 88, jl = rem % 88;
            int r = q * 176 + rk * 88 + jl;
            v = bih[r] + bhh[r];
        } else if (idx < 2389) {
            int j = idx - 1685;
            int rk = j / 352, rem = j % 352, q = rem / 88, jl = rem % 88;
            int r = q * 176 + rk * 88 + jl;
            v = bih2[r] + bhh2[r];
        }
        else if (idx < 2565)  v = Wo[idx - 2389];
        else                  v = bo[0];
        g_B[idx] = v;
    }
}

// ========================== msum precompute ===============================
__global__ void msum_kernel(const float* __restrict__ masks)
{
    __shared__ float red[256];
    int t = blockIdx.x;
    float s = 0.0f;
    for (int idx = threadIdx.x; idx < 512 * FEAT; idx += 256) {
        int b = idx / FEAT, f = idx - b * FEAT;
        s += masks[(b * SEQB + t) * FEAT + f];
    }
    red[threadIdx.x] = s;
    __syncthreads();
    for (int o = 128; o > 0; o >>= 1) {
        if (threadIdx.x < o) red[threadIdx.x] += red[threadIdx.x + o];
        __syncthreads();
    }
    if (threadIdx.x == 0) g_inv_msum[t] = 1.0f / (red[0] + 1e-5f);
}

// ========================== helpers =======================================
__device__ __forceinline__ float sigfast(float x)
{ return __fdividef(1.0f, 1.0f + __expf(-x)); }
__device__ __forceinline__ float tanhfast(float x)
{ return __fdividef(2.0f, 1.0f + __expf(-2.0f * x)) - 1.0f; }

__device__ __forceinline__ void st_peer(float* p, float v, int peer)
{
    unsigned int a = (unsigned int)__cvta_generic_to_shared(p);
    unsigned int ra;
    asm("mapa.shared::cluster.u32 %0, %1, %2;" : "=r"(ra) : "r"(a), "r"(peer));
    asm volatile("st.shared::cluster.f32 [%0], %1;" :: "r"(ra), "f"(v));
}

#define CSYNC() do { \
    asm volatile("barrier.cluster.arrive.aligned;" ::: "memory"); \
    asm volatile("barrier.cluster.wait.aligned;" ::: "memory"); } while (0)

#define FMA2(a, b, c) asm("fma.rn.f32x2 %0, %1, %2, %0;" : "+l"(a) : "l"(b), "l"(c))

// f32x2 GEMV over k-pair range [p0,p1): weights float2 [pair][Cp], input pk[k][8]
__device__ __forceinline__ void gemv8(unsigned long long acc[4],
                                      const float* __restrict__ wbase, int Cp, int col,
                                      const float* __restrict__ pk, int p0, int p1)
{
    const float2* wp = (const float2*)wbase + (size_t)p0 * Cp + col;
    const ulonglong2* ip = (const ulonglong2*)pk + 4 * p0;
#pragma unroll 4
    for (int p = p0; p < p1; p++) {
        float2 w = *wp; wp += Cp;
        ulonglong2 e0 = ip[0], e1 = ip[1], o0 = ip[2], o1 = ip[3]; ip += 4;
        unsigned long long wx, wy;
        asm("mov.b64 %0, {%1, %1};" : "=l"(wx) : "r"(__float_as_uint(w.x)));
        asm("mov.b64 %0, {%1, %1};" : "=l"(wy) : "r"(__float_as_uint(w.y)));
        FMA2(acc[0], wx, e0.x); FMA2(acc[1], wx, e0.y);
        FMA2(acc[2], wx, e1.x); FMA2(acc[3], wx, e1.y);
        FMA2(acc[0], wy, o0.x); FMA2(acc[1], wy, o0.y);
        FMA2(acc[2], wy, o1.x); FMA2(acc[3], wy, o1.y);
    }
}

// ========================== main persistent kernel ========================
struct __align__(16) SM {
    float d[164][8], m[164][8], x[164][8], gx[164][8];
    float xc[164][8], cc[164][8], xh[164][8], zh[164][8], al[164][8];
    float hd[176][8];
    float h0[2][176][8], hR[2][176][8];
    float c0[88][8], c1[88][8];
    float part[8][712];
};

__device__ __forceinline__ void store_part(SM* sm, int u, const unsigned long long acc[4])
{
#pragma unroll
    for (int bp = 0; bp < 4; bp++) {
        unsigned int lo, hi;
        asm("mov.b64 {%0, %1}, %2;" : "=r"(lo), "=r"(hi) : "l"(acc[bp]));
        sm->part[2 * bp][u]     = __uint_as_float(lo);
        sm->part[2 * bp + 1][u] = __uint_as_float(hi);
    }
}

__global__ void __launch_bounds__(NTHR, 1) __cluster_dims__(2, 1, 1)
brits_kernel(const float* __restrict__ values, const float* __restrict__ masks,
             const float* __restrict__ deltas, float* __restrict__ out)
{
    extern __shared__ char dynbuf[];
    SM* sm = (SM*)dynbuf;
    const int tid = threadIdx.x;
    unsigned int rank;
    asm("mov.u32 %0, %%cluster_ctarank;" : "=r"(rank));
    const int peer = (int)(rank ^ 1u);
    const int cid = blockIdx.x >> 1;
    const int b0 = cid * 8;

    // zero all shared state
    {
        float* sp = (float*)sm;
        for (int i = tid; i < SMEM_BYTES / 4; i += NTHR) sp[i] = 0.0f;
    }

    // prefetch slots: s0 = tid, s1 = tid + 704 (slots over 8b x 164f)
    const int s0 = tid,        b_0 = s0 / 164, f_0 = s0 % 164;
    const int s1 = tid + NTHR, b_1 = s1 / 164, f_1 = s1 % 164;
    const bool v0 = (f_0 < 161);
    const bool v1 = (s1 < 1312) && (f_1 < 161);
    float wdx0 = 0.f, bdx0 = 0.f, wdx1 = 0.f, bdx1 = 0.f;
    if (v0) { wdx0 = g_B[B_wdx + f_0]; bdx0 = g_B[B_bdx + f_0]; }
    if (v1) { wdx1 = g_B[B_wdx + f_1]; bdx1 = g_B[B_bdx + f_1]; }

    float px0 = 0.f, pm0 = 0.f, pd0 = 0.f, px1 = 0.f, pm1 = 0.f, pd1 = 0.f;
    if (v0) {
        int off = ((b0 + b_0) * SEQB + 0) * FEAT + f_0;
        px0 = values[off]; pm0 = masks[off]; pd0 = deltas[off];
    }
    if (v1) {
        int off = ((b0 + b_1) * SEQB + 0) * FEAT + f_1;
        px1 = values[off]; pm1 = masks[off]; pd1 = deltas[off];
    }

    // chunk bounds
    const int pb82[5] = {0, 21, 42, 62, 82};
    const int pb88[5] = {0, 22, 44, 66, 88};

    float lossAcc = 0.0f;
    __syncthreads();

    for (int t = 0; t < SEQB; t++) {
        const float lw = (rank == 0) ? g_inv_msum[t] : 0.0f;

        // P0: commit prefetched x/m/d(+gamma_x), issue next prefetch
        if (v0) {
            sm->x[f_0][b_0] = px0; sm->m[f_0][b_0] = pm0; sm->d[f_0][b_0] = pd0;
            sm->gx[f_0][b_0] = __expf(-fmaxf(pd0 * wdx0 + bdx0, 0.0f));
        }
        if (v1) {
            sm->x[f_1][b_1] = px1; sm->m[f_1][b_1] = pm1; sm->d[f_1][b_1] = pd1;
            sm->gx[f_1][b_1] = __expf(-fmaxf(pd1 * wdx1 + bdx1, 0.0f));
        }
        {
            int tn = (t + 1 < SEQB) ? t + 1 : SEQB - 1;
            if (v0) {
                int off = ((b0 + b_0) * SEQB + tn) * FEAT + f_0;
                px0 = values[off]; pm0 = masks[off]; pd0 = deltas[off];
            }
            if (v1) {
                int off = ((b0 + b_1) * SEQB + tn) * FEAT + f_1;
                px1 = values[off]; pm1 = masks[off]; pd1 = deltas[off];
            }
        }
        __syncthreads();

        // PA: Wdh gemv (176 rows x 4 k-chunks)
        {
            int kc = tid / 176, row = tid % 176;
            unsigned long long acc[4] = {0, 0, 0, 0};
            gemv8(acc, g_WT + A1, 176, row, &sm->d[0][0], pb82[kc], pb82[kc + 1]);
            store_part(sm, kc * 176 + row, acc);
        }
        __syncthreads();

        // PC1: gamma_h combine -> decayed h
        for (int u = tid; u < 1408; u += NTHR) {
            int j = u % 176, b = u / 176;
            float s = sm->part[b][j] + sm->part[b][176 + j]
                    + sm->part[b][352 + j] + sm->part[b][528 + j] + g_B[B_bdh + j];
            float gh = __expf(-fmaxf(s, 0.0f));
            sm->hd[j][b] = sm->hR[t & 1][j][b] * gh;
        }
        __syncthreads();

        // PB: Wwc gemv (161 rows x 4 chunks: 2 over gx, 2 over m)
        if (tid < 656) {
            int kc = tid / 164, row = tid % 164;
            if (row < 161) {
                unsigned long long acc[4] = {0, 0, 0, 0};
                if (kc < 2)
                    gemv8(acc, g_WT + A4,  164, row, &sm->gx[0][0], kc * 41, kc * 41 + 41);
                else
                    gemv8(acc, g_WT + A4b, 164, row, &sm->m[0][0], (kc - 2) * 41, (kc - 2) * 41 + 41);
                store_part(sm, kc * 164 + row, acc);
            }
        }
        __syncthreads();

        // PBc: alpha combine
        for (int u = tid; u < 1288; u += NTHR) {
            int f = u % 161, b = u / 161;
            sm->al[f][b] = sm->part[b][f] + sm->part[b][164 + f]
                         + sm->part[b][328 + f] + sm->part[b][492 + f] + g_B[B_bwc + f];
        }
        __syncthreads();

        // P2: Whr gemv (input hd, 88 pairs x 4 chunks)
        if (tid < 656) {
            int kc = tid / 164, row = tid % 164;
            if (row < 161) {
                unsigned long long acc[4] = {0, 0, 0, 0};
                gemv8(acc, g_WT + A2, 164, row, &sm->hd[0][0], pb88[kc], pb88[kc + 1]);
                store_part(sm, kc * 164 + row, acc);
            }
        }
        __syncthreads();

        // P2b: x_h, loss1, x_c
        for (int u = tid; u < 1288; u += NTHR) {
            int f = u % 161, b = u / 161;
            float xh = sm->part[b][f] + sm->part[b][164 + f]
                     + sm->part[b][328 + f] + sm->part[b][492 + f] + g_B[B_bhr + f];
            float x = sm->x[f][b], m = sm->m[f][b];
            lossAcc += fabsf(x - xh) * m * lw;
            sm->xh[f][b] = xh;
            sm->xc[f][b] = m * x + (1.0f - m) * xh;
        }
        __syncthreads();

        // P3: Wfr gemv (input xc)
        if (tid < 656) {
            int kc = tid / 164, row = tid % 164;
            if (row < 161) {
                unsigned long long acc[4] = {0, 0, 0, 0};
                gemv8(acc, g_WT + A3, 164, row, &sm->xc[0][0], pb82[kc], pb82[kc + 1]);
                store_part(sm, kc * 164 + row, acc);
            }
        }
        __syncthreads();

        // P3b: z_h, loss2
        for (int u = tid; u < 1288; u += NTHR) {
            int f = u % 161, b = u / 161;
            float zh = sm->part[b][f] + sm->part[b][164 + f]
                     + sm->part[b][328 + f] + sm->part[b][492 + f] + g_B[B_bfr + f];
            sm->zh[f][b] = zh;
            lossAcc += fabsf(sm->x[f][b] - zh) * sm->m[f][b] * lw;
        }
        __syncthreads();

        // P4b: c_h, loss3, c_c + imputation store
        for (int u = tid; u < 1288; u += NTHR) {
            int f = u % 161, b = u / 161;
            float al = sm->al[f][b];
            float xh = sm->xh[f][b];
            float ch = xh + al * (sm->zh[f][b] - xh);
            float x = sm->x[f][b], m = sm->m[f][b];
            lossAcc += fabsf(x - ch) * m * lw;
            float cc = m * x + (1.0f - m) * ch;
            sm->cc[f][b] = cc;
            if ((b >> 2) == (int)rank)
                out[513 + ((b0 + b) * SEQB + t) * FEAT + f] = cc;
        }
        __syncthreads();

        // P5: LSTM1 gates (352 local rows x 2 k-chunks)
        {
            int kh = tid / 352, lrow = tid % 352;
            int col = (int)rank * 352 + lrow;
            unsigned long long acc[4] = {0, 0, 0, 0};
            if (kh == 0) {
                gemv8(acc, g_WT + A5,  704, col, &sm->cc[0][0], 0, 82);
                gemv8(acc, g_WT + A5m, 704, col, &sm->m[0][0],  0, 44);
            } else {
                gemv8(acc, g_WT + A5m, 704, col, &sm->m[0][0], 44, 82);
                gemv8(acc, g_WT + A5h, 704, col, &sm->h0[t & 1][0][0], 0, 88);
            }
            store_part(sm, kh * 352 + lrow, acc);
        }
        __syncthreads();

        // P6: LSTM1 elementwise -> h0 new (own half, local + peer store)
        {
            int jl = tid % 88, b = tid / 88;
            float g0 = sm->part[b][jl]       + sm->part[b][352 + jl]       + g_B[B_b1 + (int)rank * 352 + jl];
            float g1 = sm->part[b][88 + jl]  + sm->part[b][352 + 88 + jl]  + g_B[B_b1 + (int)rank * 352 + 88 + jl];
            float g2 = sm->part[b][176 + jl] + sm->part[b][352 + 176 + jl] + g_B[B_b1 + (int)rank * 352 + 176 + jl];
            float g3 = sm->part[b][264 + jl] + sm->part[b][352 + 264 + jl] + g_B[B_b1 + (int)rank * 352 + 264 + jl];
            float i_ = sigfast(g0), f_ = sigfast(g1), gg = tanhfast(g2), o_ = sigfast(g3);
            float c = f_ * sm->c0[jl][b] + i_ * gg;
            sm->c0[jl][b] = c;
            float h0v = o_ * tanhfast(c);
            int idx = (int)rank * 88 + jl;
            sm->h0[(t + 1) & 1][idx][b] = h0v;
            st_peer(&sm->h0[(t + 1) & 1][idx][b], h0v, peer);
        }
        CSYNC();

        // P7: LSTM2 gates
        {
            int kh = tid / 352, lrow = tid % 352;
            int col = (int)rank * 352 + lrow;
            unsigned long long acc[4] = {0, 0, 0, 0};
            if (kh == 0)
                gemv8(acc, g_WT + A6,  704, col, &sm->h0[(t + 1) & 1][0][0], 0, 88);
            else
                gemv8(acc, g_WT + A6h, 704, col, &sm->hd[0][0], 0, 88);
            store_part(sm, kh * 352 + lrow, acc);
        }
        __syncthreads();

        // P8: LSTM2 elementwise -> h new (own half, local + peer store)
        {
            int jl = tid % 88, b = tid / 88;
            float g0 = sm->part[b][jl]       + sm->part[b][352 + jl]       + g_B[B_b2 + (int)rank * 352 + jl];
            float g1 = sm->part[b][88 + jl]  + sm->part[b][352 + 88 + jl]  + g_B[B_b2 + (int)rank * 352 + 88 + jl];
            float g2 = sm->part[b][176 + jl] + sm->part[b][352 + 176 + jl] + g_B[B_b2 + (int)rank * 352 + 176 + jl];
            float g3 = sm->part[b][264 + jl] + sm->part[b][352 + 264 + jl] + g_B[B_b2 + (int)rank * 352 + 264 + jl];
            float i_ = sigfast(g0), f_ = sigfast(g1), gg = tanhfast(g2), o_ = sigfast(g3);
            float c = f_ * sm->c1[jl][b] + i_ * gg;
            sm->c1[jl][b] = c;
            float hv = o_ * tanhfast(c);
            int idx = (int)rank * 88 + jl;
            sm->hR[(t + 1) & 1][idx][b] = hv;
            st_peer(&sm->hR[(t + 1) & 1][idx][b], hv, peer);
        }
        CSYNC();
    }

    // predictions: final h is in hR[SEQB & 1] == hR[0]
    if (rank == 0 && tid < 256) {
        int b = tid >> 5, lane = tid & 31;
        float s = 0.0f;
        for (int j = lane; j < 176; j += 32) s += sm->hR[0][j][b] * g_B[B_Wo + j];
        for (int o = 16; o; o >>= 1) s += __shfl_down_sync(0xffffffffu, s, o);
        if (lane == 0) out[1 + b0 + b] = sigfast(s + g_B[B_bo]);
    }

    // loss partial
    {
        float* lr = &sm->part[0][0];
        lr[tid] = lossAcc;
        __syncthreads();
        if (tid == 0 && rank == 0) {
            float s = 0.0f;
            for (int i = 0; i < NTHR; i++) s += lr[i];
            g_lossp[cid] = s;
        }
    }
}

__global__ void finalize_kernel(float* __restrict__ out)
{
    if (threadIdx.x == 0 && blockIdx.x == 0) {
        float s = 0.0f;
        for (int i = 0; i < NCLUS; i++) s += g_lossp[i];
        out[0] = s / (float)SEQB;
    }
}

extern "C" void kernel_launch(void* const* d_in, const int* in_sizes, int n_in,
                              void* d_out, int out_size)
{
    const float* values = (const float*)d_in[0];
    const float* masks  = (const float*)d_in[1];
    const float* deltas = (const float*)d_in[2];
    const float* Wdh  = (const float*)d_in[5];
    const float* bdh  = (const float*)d_in[6];
    const float* Wdx  = (const float*)d_in[7];
    const float* bdx  = (const float*)d_in[8];
    const float* Whr  = (const float*)d_in[9];
    const float* bhr  = (const float*)d_in[10];
    const float* Wfr  = (const float*)d_in[11];
    const float* bfr  = (const float*)d_in[12];
    const float* Wwc  = (const float*)d_in[13];
    const float* bwc  = (const float*)d_in[14];
    const float* Wih  = (const float*)d_in[15];
    const float* Whh  = (const float*)d_in[16];
    const float* bih  = (const float*)d_in[17];
    const float* bhh  = (const float*)d_in[18];
    const float* Wih2 = (const float*)d_in[19];
    const float* Whh2 = (const float*)d_in[20];
    const float* bih2 = (const float*)d_in[21];
    const float* bhh2 = (const float*)d_in[22];
    const float* Wo   = (const float*)d_in[23];
    const float* bo   = (const float*)d_in[24];
    float* out = (float*)d_out;

    cudaFuncSetAttribute(brits_kernel, cudaFuncAttributeMaxDynamicSharedMemorySize, SMEM_BYTES);

    repack_kernel<<<960, 256>>>(Wdh, Whr, Wfr, Wwc, Wih, Whh, Wih2, Whh2,
                                bdh, Wdx, bdx, bhr, bfr, bwc,
                                bih, bhh, bih2, bhh2, Wo, bo);
    msum_kernel<<<SEQB, 256>>>(masks);
    brits_kernel<<<NCTA, NTHR, SMEM_BYTES>>>(values, masks, deltas, out);
    finalize_kernel<<<1, 32>>>(out);
}

// round 9
// speedup vs baseline: 1.0005x; 1.0005x over previous
#include <cuda_runtime.h>

#define FEAT 161
#define HID  176
#define SEQB 456
#define NTHR 704
#define NCTA 128
#define NCLUS 64

// ---- float2-packed transposed weight offsets (float units) ----
// layout per region: float2 element (pair p, col c) at base + (p*Cp + c)*2
#define A1  0        // Wdh : 82 pairs, Cp=176
#define A2  28864    // Whr : 88 pairs, Cp=164
#define A3  57728    // Wfr : 82 pairs, Cp=164
#define A4  84624    // Wwc gx seg: 82 pairs, Cp=164
#define A4b 111520   // Wwc m  seg: 82 pairs, Cp=164
#define A5  138416   // LSTM1 cc seg: 82 pairs, Cp=704 (cols permuted)
#define A5m 253872   // LSTM1 m  seg: 82 pairs, Cp=704
#define A5h 369328   // LSTM1 h0 seg: 88 pairs, Cp=704
#define A6  493232   // LSTM2 h0 seg: 88 pairs, Cp=704
#define A6h 617136   // LSTM2 hd seg: 88 pairs, Cp=704
#define WT_TOTAL 741040

// ---- bias offsets ----
#define B_bdh 0
#define B_wdx 176
#define B_bdx 337
#define B_bhr 498
#define B_bfr 659
#define B_bwc 820
#define B_b1  981
#define B_b2  1685
#define B_Wo  2389
#define B_bo  2565
#define B_TOTAL 2566

#define SMEM_BYTES 103808

__device__ float g_WT[WT_TOTAL];
__device__ float g_B[B_TOTAL];
__device__ float g_inv_msum[SEQB];
__device__ float g_lossp[NCLUS];

// ============================= repack =====================================
__global__ void repack_kernel(
    const float* __restrict__ Wdh, const float* __restrict__ Whr,
    const float* __restrict__ Wfr, const float* __restrict__ Wwc,
    const float* __restrict__ Wih, const float* __restrict__ Whh,
    const float* __restrict__ Wih2, const float* __restrict__ Whh2,
    const float* __restrict__ bdh, const float* __restrict__ Wdx,
    const float* __restrict__ bdx, const float* __restrict__ bhr,
    const float* __restrict__ bfr, const float* __restrict__ bwc,
    const float* __restrict__ bih, const float* __restrict__ bhh,
    const float* __restrict__ bih2, const float* __restrict__ bhh2,
    const float* __restrict__ Wo, const float* __restrict__ bo)
{
    int stride = gridDim.x * blockDim.x;
    for (int idx = blockIdx.x * blockDim.x + threadIdx.x; idx < WT_TOTAL; idx += stride) {
        float v = 0.0f;
        int base, Cp, region;
        if      (idx < A2)  { base = A1;  Cp = 176; region = 0; }
        else if (idx < A3)  { base = A2;  Cp = 164; region = 1; }
        else if (idx < A4)  { base = A3;  Cp = 164; region = 2; }
        else if (idx < A4b) { base = A4;  Cp = 164; region = 3; }
        else if (idx < A5)  { base = A4b; Cp = 164; region = 4; }
        else if (idx < A5m) { base = A5;  Cp = 704; region = 5; }
        else if (idx < A5h) { base = A5m; Cp = 704; region = 6; }
        else if (idx < A6)  { base = A5h; Cp = 704; region = 7; }
        else if (idx < A6h) { base = A6;  Cp = 704; region = 8; }
        else                { base = A6h; Cp = 704; region = 9; }
        int j = idx - base, pc = j >> 1, half = j & 1;
        int p = pc / Cp, c = pc % Cp;
        int k = 2 * p + half;
        if (region >= 5) {
            // permuted LSTM column -> original gate row
            int rk = c / 352, rem = c % 352, q = rem / 88, jl = rem % 88;
            int r = q * 176 + rk * 88 + jl;
            switch (region) {
                case 5: if (k < 161) v = Wih[r * 322 + k]; break;
                case 6: if (k < 161) v = Wih[r * 322 + 161 + k]; break;
                case 7: v = Whh[r * 176 + k]; break;
                case 8: v = Wih2[r * 176 + k]; break;
                case 9: v = Whh2[r * 176 + k]; break;
            }
        } else {
            switch (region) {
                case 0: if (k < 161) v = Wdh[c * 161 + k]; break;
                case 1: if (c < 161) v = Whr[c * 176 + k]; break;
                case 2: if (c < 161 && k < 161 && k != c) v = Wfr[c * 161 + k]; break;
                case 3: if (c < 161 && k < 161) v = Wwc[c * 322 + k]; break;
                case 4: if (c < 161 && k < 161) v = Wwc[c * 322 + 161 + k]; break;
            }
        }
        g_WT[idx] = v;
    }
    for (int idx = blockIdx.x * blockDim.x + threadIdx.x; idx < B_TOTAL; idx += stride) {
        float v;
        if (idx < 176)        v = bdh[idx];
        else if (idx < 337)   { int f = idx - 176; v = Wdx[f * 161 + f]; }
        else if (idx < 498)   v = bdx[idx - 337];
        else if (idx < 659)   v = bhr[idx - 498];
        else if (idx < 820)   v = bfr[idx - 659];
        else if (idx < 981)   v = bwc[idx - 820];
        else if (idx < 1685)  {
            int j = idx - 981;
            int rk = j / 352, rem = j % 352, q = rem / 88, jl = rem % 88;
            int r = q * 176 + rk * 88 + jl;
            v = bih[r] + bhh[r];
        } else if (idx < 2389) {
            int j = idx - 1685;
            int rk = j / 352, rem = j % 352, q = rem / 88, jl = rem % 88;
            int r = q * 176 + rk * 88 + jl;
            v = bih2[r] + bhh2[r];
        }
        else if (idx < 2565)  v = Wo[idx - 2389];
        else                  v = bo[0];
        g_B[idx] = v;
    }
}

// ========================== msum precompute ===============================
__global__ void msum_kernel(const float* __restrict__ masks)
{
    __shared__ float red[256];
    int t = blockIdx.x;
    float s = 0.0f;
    for (int idx = threadIdx.x; idx < 512 * FEAT; idx += 256) {
        int b = idx / FEAT, f = idx - b * FEAT;
        s += masks[(b * SEQB + t) * FEAT + f];
    }
    red[threadIdx.x] = s;
    __syncthreads();
    for (int o = 128; o > 0; o >>= 1) {
        if (threadIdx.x < o) red[threadIdx.x] += red[threadIdx.x + o];
        __syncthreads();
    }
    if (threadIdx.x == 0) g_inv_msum[t] = 1.0f / (red[0] + 1e-5f);
}

// ========================== helpers =======================================
__device__ __forceinline__ float sigfast(float x)
{ return __fdividef(1.0f, 1.0f + __expf(-x)); }
__device__ __forceinline__ float tanhfast(float x)
{ return __fdividef(2.0f, 1.0f + __expf(-2.0f * x)) - 1.0f; }

__device__ __forceinline__ void st_peer(float* p, float v, int peer)
{
    unsigned int a = (unsigned int)__cvta_generic_to_shared(p);
    unsigned int ra;
    asm("mapa.shared::cluster.u32 %0, %1, %2;" : "=r"(ra) : "r"(a), "r"(peer));
    asm volatile("st.shared::cluster.f32 [%0], %1;" :: "r"(ra), "f"(v));
}

#define CSYNC() do { \
    asm volatile("barrier.cluster.arrive.aligned;" ::: "memory"); \
    asm volatile("barrier.cluster.wait.aligned;" ::: "memory"); } while (0)

#define FMA2(a, b, c) asm("fma.rn.f32x2 %0, %1, %2, %0;" : "+l"(a) : "l"(b), "l"(c))

// f32x2 GEMV over k-pair range [p0,p1): weights float2 [pair][Cp], input pk[k][8]
__device__ __forceinline__ void gemv8(unsigned long long acc[4],
                                      const float* __restrict__ wbase, int Cp, int col,
                                      const float* __restrict__ pk, int p0, int p1)
{
    const float2* wp = (const float2*)wbase + (size_t)p0 * Cp + col;
    const ulonglong2* ip = (const ulonglong2*)pk + 4 * p0;
#pragma unroll 4
    for (int p = p0; p < p1; p++) {
        float2 w = *wp; wp += Cp;
        ulonglong2 e0 = ip[0], e1 = ip[1], o0 = ip[2], o1 = ip[3]; ip += 4;
        unsigned long long wx, wy;
        asm("mov.b64 %0, {%1, %1};" : "=l"(wx) : "r"(__float_as_uint(w.x)));
        asm("mov.b64 %0, {%1, %1};" : "=l"(wy) : "r"(__float_as_uint(w.y)));
        FMA2(acc[0], wx, e0.x); FMA2(acc[1], wx, e0.y);
        FMA2(acc[2], wx, e1.x); FMA2(acc[3], wx, e1.y);
        FMA2(acc[0], wy, o0.x); FMA2(acc[1], wy, o0.y);
        FMA2(acc[2], wy, o1.x); FMA2(acc[3], wy, o1.y);
    }
}

// ========================== main persistent kernel ========================
struct __align__(16) SM {
    float d[164][8], m[164][8], x[164][8], gx[164][8];
    float xc[164][8], cc[164][8], xh[164][8], zh[164][8], al[164][8];
    float hd[176][8];
    float h0[2][176][8], hR[2][176][8];
    float c0[88][8], c1[88][8];
    float part[8][712];
};

__device__ __forceinline__ void store_part(SM* sm, int u, const unsigned long long acc[4])
{
#pragma unroll
    for (int bp = 0; bp < 4; bp++) {
        unsigned int lo, hi;
        asm("mov.b64 {%0, %1}, %2;" : "=r"(lo), "=r"(hi) : "l"(acc[bp]));
        sm->part[2 * bp][u]     = __uint_as_float(lo);
        sm->part[2 * bp + 1][u] = __uint_as_float(hi);
    }
}

__global__ void __launch_bounds__(NTHR, 1) __cluster_dims__(2, 1, 1)
brits_kernel(const float* __restrict__ values, const float* __restrict__ masks,
             const float* __restrict__ deltas, float* __restrict__ out)
{
    extern __shared__ char dynbuf[];
    SM* sm = (SM*)dynbuf;
    const int tid = threadIdx.x;
    unsigned int rank;
    asm("mov.u32 %0, %%cluster_ctarank;" : "=r"(rank));
    const int peer = (int)(rank ^ 1u);
    const int cid = blockIdx.x >> 1;
    const int b0 = cid * 8;

    // zero all shared state
    {
        float* sp = (float*)sm;
        for (int i = tid; i < SMEM_BYTES / 4; i += NTHR) sp[i] = 0.0f;
    }

    // prefetch slots: s0 = tid, s1 = tid + 704 (slots over 8b x 164f)
    const int s0 = tid,        b_0 = s0 / 164, f_0 = s0 % 164;
    const int s1 = tid + NTHR, b_1 = s1 / 164, f_1 = s1 % 164;
    const bool v0 = (f_0 < 161);
    const bool v1 = (s1 < 1312) && (f_1 < 161);
    float wdx0 = 0.f, bdx0 = 0.f, wdx1 = 0.f, bdx1 = 0.f;
    if (v0) { wdx0 = g_B[B_wdx + f_0]; bdx0 = g_B[B_bdx + f_0]; }
    if (v1) { wdx1 = g_B[B_wdx + f_1]; bdx1 = g_B[B_bdx + f_1]; }

    float px0 = 0.f, pm0 = 0.f, pd0 = 0.f, px1 = 0.f, pm1 = 0.f, pd1 = 0.f;
    if (v0) {
        int off = ((b0 + b_0) * SEQB + 0) * FEAT + f_0;
        px0 = values[off]; pm0 = masks[off]; pd0 = deltas[off];
    }
    if (v1) {
        int off = ((b0 + b_1) * SEQB + 0) * FEAT + f_1;
        px1 = values[off]; pm1 = masks[off]; pd1 = deltas[off];
    }

    // chunk bounds
    const int pb82[5] = {0, 21, 42, 62, 82};
    const int pb88[5] = {0, 22, 44, 66, 88};

    float lossAcc = 0.0f;
    __syncthreads();

    for (int t = 0; t < SEQB; t++) {
        const float lw = (rank == 0) ? g_inv_msum[t] : 0.0f;

        // P0: commit prefetched x/m/d(+gamma_x), issue next prefetch
        if (v0) {
            sm->x[f_0][b_0] = px0; sm->m[f_0][b_0] = pm0; sm->d[f_0][b_0] = pd0;
            sm->gx[f_0][b_0] = __expf(-fmaxf(pd0 * wdx0 + bdx0, 0.0f));
        }
        if (v1) {
            sm->x[f_1][b_1] = px1; sm->m[f_1][b_1] = pm1; sm->d[f_1][b_1] = pd1;
            sm->gx[f_1][b_1] = __expf(-fmaxf(pd1 * wdx1 + bdx1, 0.0f));
        }
        {
            int tn = (t + 1 < SEQB) ? t + 1 : SEQB - 1;
            if (v0) {
                int off = ((b0 + b_0) * SEQB + tn) * FEAT + f_0;
                px0 = values[off]; pm0 = masks[off]; pd0 = deltas[off];
            }
            if (v1) {
                int off = ((b0 + b_1) * SEQB + tn) * FEAT + f_1;
                px1 = values[off]; pm1 = masks[off]; pd1 = deltas[off];
            }
        }
        __syncthreads();

        // PA: Wdh gemv (176 rows x 4 k-chunks)
        {
            int kc = tid / 176, row = tid % 176;
            unsigned long long acc[4] = {0, 0, 0, 0};
            gemv8(acc, g_WT + A1, 176, row, &sm->d[0][0], pb82[kc], pb82[kc + 1]);
            store_part(sm, kc * 176 + row, acc);
        }
        __syncthreads();

        // PC1: gamma_h combine -> decayed h
        for (int u = tid; u < 1408; u += NTHR) {
            int j = u % 176, b = u / 176;
            float s = sm->part[b][j] + sm->part[b][176 + j]
                    + sm->part[b][352 + j] + sm->part[b][528 + j] + g_B[B_bdh + j];
            float gh = __expf(-fmaxf(s, 0.0f));
            sm->hd[j][b] = sm->hR[t & 1][j][b] * gh;
        }
        __syncthreads();

        // PB: Wwc gemv (161 rows x 4 chunks: 2 over gx, 2 over m)
        if (tid < 656) {
            int kc = tid / 164, row = tid % 164;
            if (row < 161) {
                unsigned long long acc[4] = {0, 0, 0, 0};
                if (kc < 2)
                    gemv8(acc, g_WT + A4,  164, row, &sm->gx[0][0], kc * 41, kc * 41 + 41);
                else
                    gemv8(acc, g_WT + A4b, 164, row, &sm->m[0][0], (kc - 2) * 41, (kc - 2) * 41 + 41);
                store_part(sm, kc * 164 + row, acc);
            }
        }
        __syncthreads();

        // PBc: alpha combine
        for (int u = tid; u < 1288; u += NTHR) {
            int f = u % 161, b = u / 161;
            sm->al[f][b] = sm->part[b][f] + sm->part[b][164 + f]
                         + sm->part[b][328 + f] + sm->part[b][492 + f] + g_B[B_bwc + f];
        }
        __syncthreads();

        // P2: Whr gemv (input hd, 88 pairs x 4 chunks)
        if (tid < 656) {
            int kc = tid / 164, row = tid % 164;
            if (row < 161) {
                unsigned long long acc[4] = {0, 0, 0, 0};
                gemv8(acc, g_WT + A2, 164, row, &sm->hd[0][0], pb88[kc], pb88[kc + 1]);
                store_part(sm, kc * 164 + row, acc);
            }
        }
        __syncthreads();

        // P2b: x_h, loss1, x_c
        for (int u = tid; u < 1288; u += NTHR) {
            int f = u % 161, b = u / 161;
            float xh = sm->part[b][f] + sm->part[b][164 + f]
                     + sm->part[b][328 + f] + sm->part[b][492 + f] + g_B[B_bhr + f];
            float x = sm->x[f][b], m = sm->m[f][b];
            lossAcc += fabsf(x - xh) * m * lw;
            sm->xh[f][b] = xh;
            sm->xc[f][b] = m * x + (1.0f - m) * xh;
        }
        __syncthreads();

        // P3: Wfr gemv (input xc)
        if (tid < 656) {
            int kc = tid / 164, row = tid % 164;
            if (row < 161) {
                unsigned long long acc[4] = {0, 0, 0, 0};
                gemv8(acc, g_WT + A3, 164, row, &sm->xc[0][0], pb82[kc], pb82[kc + 1]);
                store_part(sm, kc * 164 + row, acc);
            }
        }
        __syncthreads();

        // P3b: z_h, loss2
        for (int u = tid; u < 1288; u += NTHR) {
            int f = u % 161, b = u / 161;
            float zh = sm->part[b][f] + sm->part[b][164 + f]
                     + sm->part[b][328 + f] + sm->part[b][492 + f] + g_B[B_bfr + f];
            sm->zh[f][b] = zh;
            lossAcc += fabsf(sm->x[f][b] - zh) * sm->m[f][b] * lw;
        }
        __syncthreads();

        // P4b: c_h, loss3, c_c + imputation store
        for (int u = tid; u < 1288; u += NTHR) {
            int f = u % 161, b = u / 161;
            float al = sm->al[f][b];
            float xh = sm->xh[f][b];
            float ch = xh + al * (sm->zh[f][b] - xh);
            float x = sm->x[f][b], m = sm->m[f][b];
            lossAcc += fabsf(x - ch) * m * lw;
            float cc = m * x + (1.0f - m) * ch;
            sm->cc[f][b] = cc;
            if ((b >> 2) == (int)rank)
                out[513 + ((b0 + b) * SEQB + t) * FEAT + f] = cc;
        }
        __syncthreads();

        // P5: LSTM1 gates (352 local rows x 2 k-chunks)
        {
            int kh = tid / 352, lrow = tid % 352;
            int col = (int)rank * 352 + lrow;
            unsigned long long acc[4] = {0, 0, 0, 0};
            if (kh == 0) {
                gemv8(acc, g_WT + A5,  704, col, &sm->cc[0][0], 0, 82);
                gemv8(acc, g_WT + A5m, 704, col, &sm->m[0][0],  0, 44);
            } else {
                gemv8(acc, g_WT + A5m, 704, col, &sm->m[0][0], 44, 82);
                gemv8(acc, g_WT + A5h, 704, col, &sm->h0[t & 1][0][0], 0, 88);
            }
            store_part(sm, kh * 352 + lrow, acc);
        }
        __syncthreads();

        // P6: LSTM1 elementwise -> h0 new (own half, local + peer store)
        {
            int jl = tid % 88, b = tid / 88;
            float g0 = sm->part[b][jl]       + sm->part[b][352 + jl]       + g_B[B_b1 + (int)rank * 352 + jl];
            float g1 = sm->part[b][88 + jl]  + sm->part[b][352 + 88 + jl]  + g_B[B_b1 + (int)rank * 352 + 88 + jl];
            float g2 = sm->part[b][176 + jl] + sm->part[b][352 + 176 + jl] + g_B[B_b1 + (int)rank * 352 + 176 + jl];
            float g3 = sm->part[b][264 + jl] + sm->part[b][352 + 264 + jl] + g_B[B_b1 + (int)rank * 352 + 264 + jl];
            float i_ = sigfast(g0), f_ = sigfast(g1), gg = tanhfast(g2), o_ = sigfast(g3);
            float c = f_ * sm->c0[jl][b] + i_ * gg;
            sm->c0[jl][b] = c;
            float h0v = o_ * tanhfast(c);
            int idx = (int)rank * 88 + jl;
            sm->h0[(t + 1) & 1][idx][b] = h0v;
            st_peer(&sm->h0[(t + 1) & 1][idx][b], h0v, peer);
        }
        CSYNC();

        // P7: LSTM2 gates
        {
            int kh = tid / 352, lrow = tid % 352;
            int col = (int)rank * 352 + lrow;
            unsigned long long acc[4] = {0, 0, 0, 0};
            if (kh == 0)
                gemv8(acc, g_WT + A6,  704, col, &sm->h0[(t + 1) & 1][0][0], 0, 88);
            else
                gemv8(acc, g_WT + A6h, 704, col, &sm->hd[0][0], 0, 88);
            store_part(sm, kh * 352 + lrow, acc);
        }
        __syncthreads();

        // P8: LSTM2 elementwise -> h new (own half, local + peer store)
        {
            int jl = tid % 88, b = tid / 88;
            float g0 = sm->part[b][jl]       + sm->part[b][352 + jl]       + g_B[B_b2 + (int)rank * 352 + jl];
            float g1 = sm->part[b][88 + jl]  + sm->part[b][352 + 88 + jl]  + g_B[B_b2 + (int)rank * 352 + 88 + jl];
            float g2 = sm->part[b][176 + jl] + sm->part[b][352 + 176 + jl] + g_B[B_b2 + (int)rank * 352 + 176 + jl];
            float g3 = sm->part[b][264 + jl] + sm->part[b][352 + 264 + jl] + g_B[B_b2 + (int)rank * 352 + 264 + jl];
            float i_ = sigfast(g0), f_ = sigfast(g1), gg = tanhfast(g2), o_ = sigfast(g3);
            float c = f_ * sm->c1[jl][b] + i_ * gg;
            sm->c1[jl][b] = c;
            float hv = o_ * tanhfast(c);
            int idx = (int)rank * 88 + jl;
            sm->hR[(t + 1) & 1][idx][b] = hv;
            st_peer(&sm->hR[(t + 1) & 1][idx][b], hv, peer);
        }
        CSYNC();
    }

    // predictions: final h is in hR[SEQB & 1] == hR[0]
    if (rank == 0 && tid < 256) {
        int b = tid >> 5, lane = tid & 31;
        float s = 0.0f;
        for (int j = lane; j < 176; j += 32) s += sm->hR[0][j][b] * g_B[B_Wo + j];
        for (int o = 16; o; o >>= 1) s += __shfl_down_sync(0xffffffffu, s, o);
        if (lane == 0) out[1 + b0 + b] = sigfast(s + g_B[B_bo]);
    }

    // loss partial
    {
        float* lr = &sm->part[0][0];
        lr[tid] = lossAcc;
        __syncthreads();
        if (tid == 0 && rank == 0) {
            float s = 0.0f;
            for (int i = 0; i < NTHR; i++) s += lr[i];
            g_lossp[cid] = s;
        }
    }
}

__global__ void finalize_kernel(float* __restrict__ out)
{
    if (threadIdx.x == 0 && blockIdx.x == 0) {
        float s = 0.0f;
        for (int i = 0; i < NCLUS; i++) s += g_lossp[i];
        out[0] = s / (float)SEQB;
    }
}

extern "C" void kernel_launch(void* const* d_in, const int* in_sizes, int n_in,
                              void* d_out, int out_size)
{
    const float* values = (const float*)d_in[0];
    const float* masks  = (const float*)d_in[1];
    const float* deltas = (const float*)d_in[2];
    const float* Wdh  = (const float*)d_in[5];
    const float* bdh  = (const float*)d_in[6];
    const float* Wdx  = (const float*)d_in[7];
    const float* bdx  = (const float*)d_in[8];
    const float* Whr  = (const float*)d_in[9];
    const float* bhr  = (const float*)d_in[10];
    const float* Wfr  = (const float*)d_in[11];
    const float* bfr  = (const float*)d_in[12];
    const float* Wwc  = (const float*)d_in[13];
    const float* bwc  = (const float*)d_in[14];
    const float* Wih  = (const float*)d_in[15];
    const float* Whh  = (const float*)d_in[16];
    const float* bih  = (const float*)d_in[17];
    const float* bhh  = (const float*)d_in[18];
    const float* Wih2 = (const float*)d_in[19];
    const float* Whh2 = (const float*)d_in[20];
    const float* bih2 = (const float*)d_in[21];
    const float* bhh2 = (const float*)d_in[22];
    const float* Wo   = (const float*)d_in[23];
    const float* bo   = (const float*)d_in[24];
    float* out = (float*)d_out;

    cudaFuncSetAttribute(brits_kernel, cudaFuncAttributeMaxDynamicSharedMemorySize, SMEM_BYTES);

    repack_kernel<<<960, 256>>>(Wdh, Whr, Wfr, Wwc, Wih, Whh, Wih2, Whh2,
                                bdh, Wdx, bdx, bhr, bfr, bwc,
                                bih, bhh, bih2, bhh2, Wo, bo);
    msum_kernel<<<SEQB, 256>>>(masks);
    brits_kernel<<<NCTA, NTHR, SMEM_BYTES>>>(values, masks, deltas, out);
    finalize_kernel<<<1, 32>>>(out);
}